// round 16
// baseline (speedup 1.0000x reference)
#include <cuda_runtime.h>
#include <math.h>

// Problem constants: B=32, S=512, D=1024, H=1024, gates=3H=3072
#define GRU_B 32
#define GRU_S 512
#define GRU_D 1024
#define GRU_H 1024
#define GRU_G 3072

#define STEP_BLOCKS 128

typedef unsigned long long ull;

// Scratch (allocation-free rule: __device__ globals)
__device__ float g_gi[(size_t)GRU_B * GRU_S * GRU_G];   // [B,S,3H] input projections
__device__ float g_h[2][GRU_B * GRU_H];                  // ping-pong hidden state
__device__ unsigned g_bar_count;
__device__ unsigned g_bar_gen;

// ---------------- packed f32x2 helpers (sm_103a FFMA2) ----------------
__device__ __forceinline__ ull ffma2(ull a, ull b, ull c) {
    ull d;
    asm("fma.rn.f32x2 %0, %1, %2, %3;" : "=l"(d) : "l"(a), "l"(b), "l"(c));
    return d;
}
__device__ __forceinline__ ull add2(ull a, ull b) {
    ull d;
    asm("add.rn.f32x2 %0, %1, %2;" : "=l"(d) : "l"(a), "l"(b));
    return d;
}
__device__ __forceinline__ ull dup2(float x) {
    ull r;
    asm("mov.b64 %0, {%1, %1};" : "=l"(r) : "f"(x));
    return r;
}
union U2 { ull u; float2 f; };
__device__ __forceinline__ float sum2(ull v) {
    U2 t; t.u = v; return t.f.x + t.f.y;
}

// ----------------------------------------------------------------------
// Phase 1: gi = feats @ Wih^T + bias (unchanged — ~95% of FFMA2 roofline)
// ----------------------------------------------------------------------
__global__ void __launch_bounds__(256, 2) gemm_ih_kernel(
    const float* __restrict__ A,     // feats [M, 1024]
    const float* __restrict__ W,     // weight_ih [3072, 1024]
    const float* __restrict__ bias)  // bias_ih [3072]
{
    __shared__ __align__(16) float As[16][128];
    __shared__ __align__(16) float Bs[16][128];

    const int tid = threadIdx.x;
    const int bm = blockIdx.y * 128;
    const int bn = blockIdx.x * 128;
    const int tm = (tid >> 4) << 3;
    const int tn = (tid & 15) << 3;
    const int lm = tid >> 2;
    const int lk = (tid & 3) << 2;

    ull acc[8][4];
#pragma unroll
    for (int i = 0; i < 8; i++)
#pragma unroll
        for (int j = 0; j < 4; j++) acc[i][j] = 0ull;

    const float* Ap = A + (size_t)(bm + lm) * GRU_D + lk;
    const float* Wp = W + (size_t)(bn + lm) * GRU_D + lk;

    for (int k0 = 0; k0 < GRU_D; k0 += 16) {
        float4 a0 = *(const float4*)(Ap + k0);
        float4 a1 = *(const float4*)(Ap + k0 + (size_t)64 * GRU_D);
        float4 w0 = *(const float4*)(Wp + k0);
        float4 w1 = *(const float4*)(Wp + k0 + (size_t)64 * GRU_D);

        As[lk + 0][lm] = a0.x; As[lk + 1][lm] = a0.y;
        As[lk + 2][lm] = a0.z; As[lk + 3][lm] = a0.w;
        As[lk + 0][lm + 64] = a1.x; As[lk + 1][lm + 64] = a1.y;
        As[lk + 2][lm + 64] = a1.z; As[lk + 3][lm + 64] = a1.w;

        Bs[lk + 0][lm] = w0.x; Bs[lk + 1][lm] = w0.y;
        Bs[lk + 2][lm] = w0.z; Bs[lk + 3][lm] = w0.w;
        Bs[lk + 0][lm + 64] = w1.x; Bs[lk + 1][lm + 64] = w1.y;
        Bs[lk + 2][lm + 64] = w1.z; Bs[lk + 3][lm + 64] = w1.w;

        __syncthreads();

#pragma unroll
        for (int kk = 0; kk < 16; kk++) {
            float4 av0 = *(const float4*)&As[kk][tm];
            float4 av1 = *(const float4*)&As[kk][tm + 4];
            ulonglong2 bv0 = *(const ulonglong2*)&Bs[kk][tn];
            ulonglong2 bv1 = *(const ulonglong2*)&Bs[kk][tn + 4];
            float av[8] = {av0.x, av0.y, av0.z, av0.w, av1.x, av1.y, av1.z, av1.w};
#pragma unroll
            for (int i = 0; i < 8; i++) {
                ull ad = dup2(av[i]);
                acc[i][0] = ffma2(ad, bv0.x, acc[i][0]);
                acc[i][1] = ffma2(ad, bv0.y, acc[i][1]);
                acc[i][2] = ffma2(ad, bv1.x, acc[i][2]);
                acc[i][3] = ffma2(ad, bv1.y, acc[i][3]);
            }
        }
        __syncthreads();
    }

    float bz[8];
#pragma unroll
    for (int j = 0; j < 8; j++) bz[j] = bias[bn + tn + j];

#pragma unroll
    for (int i = 0; i < 8; i++) {
        float* Crow = g_gi + (size_t)(bm + tm + i) * GRU_G + bn + tn;
        U2 t0, t1, t2, t3;
        t0.u = acc[i][0]; t1.u = acc[i][1]; t2.u = acc[i][2]; t3.u = acc[i][3];
        float4 o0 = make_float4(t0.f.x + bz[0], t0.f.y + bz[1],
                                t1.f.x + bz[2], t1.f.y + bz[3]);
        float4 o1 = make_float4(t2.f.x + bz[4], t2.f.y + bz[5],
                                t3.f.x + bz[6], t3.f.y + bz[7]);
        *(float4*)(Crow + 0) = o0;
        *(float4*)(Crow + 4) = o1;
    }
}

// ----------------------------------------------------------------------
// Phase 2: PERSISTENT recurrence kernel. One launch, 512 steps, software
// grid barrier between steps. 128 blocks x 256 threads (all co-resident:
// grid <= #SMs). Block owns 8 hidden cols = 24 Whh rows (L1-resident
// across steps). Warp tile: 12 rows x 8 batches, lanes lane-interleaved
// over K (coalesced), f32x2 accumulation, warp reduce-scatter via shfl.
// ----------------------------------------------------------------------
__device__ __forceinline__ void grid_barrier(int tid, unsigned target) {
    __syncthreads();
    if (tid == 0) {
        __threadfence();
        unsigned old = atomicAdd(&g_bar_count, 1u);
        if (old == STEP_BLOCKS - 1) {
            atomicExch(&g_bar_count, 0u);
            __threadfence();
            atomicExch(&g_bar_gen, target);
        } else {
            while (atomicAdd(&g_bar_gen, 0u) < target) { __nanosleep(32); }
            __threadfence();
        }
    }
    __syncthreads();
}

#define RSTAGE(HALF, SPAN)                                                   \
    {                                                                        \
        const bool up = (lane & (SPAN)) != 0;                                \
        _Pragma("unroll")                                                    \
        for (int i = 0; i < (HALF); i++) {                                   \
            ull keep = up ? acc[i + (HALF)] : acc[i];                        \
            ull send = up ? acc[i] : acc[i + (HALF)];                        \
            ull recv = __shfl_xor_sync(0xffffffffu, send, (SPAN));           \
            acc[i] = add2(keep, recv);                                       \
        }                                                                    \
    }

__global__ void __launch_bounds__(256, 1) gru_persistent_kernel(
    const float* __restrict__ Whh,      // [3072, 1024]
    const float* __restrict__ bias_hh,  // [3072]
    float* __restrict__ out)            // [B, S, H]
{
    __shared__ float ghs[24][36];   // [local_row][batch], padded: conflict-free reads

    const int tid = threadIdx.x;
    const int warp = tid >> 5;
    const int lane = tid & 31;
    const int rg = warp >> 2;       // row group: 0 or 1 (12 rows each)
    const int bg = warp & 3;        // batch group: 8 batches each
    const int c0 = blockIdx.x * 8;  // hidden-column base

    // ---- epilogue mapping: ej = col (fast, coalesced-ish gmem), eb = batch
    const int ej = tid & 7;
    const int eb = tid >> 3;        // 0..31
    const float bh_r = bias_hh[c0 + ej];
    const float bh_i = bias_hh[GRU_H + c0 + ej];
    const float bh_n = bias_hh[2 * GRU_H + c0 + ej];
    const float* gi_base = g_gi + (size_t)eb * GRU_S * GRU_G + c0 + ej;
    float* out_base = out + (size_t)eb * GRU_S * GRU_H + c0 + ej;
    const int ehoff = eb * GRU_H + c0 + ej;

    // ---- dot-loop row offsets (floats) for this warp's 12 rows
    unsigned rowoff[12];
#pragma unroll
    for (int rr = 0; rr < 12; rr++) {
        int lr = rg * 12 + rr;             // local row 0..23
        int gate = lr >> 3, j = lr & 7;
        rowoff[rr] = (unsigned)(gate * (GRU_H * GRU_H) + (c0 + j) * GRU_H);
    }
    const int hboff = (bg * 8) * GRU_H;

    for (int s = 0; s < GRU_S; s++) {
        const float* __restrict__ h_prev = g_h[s & 1];
        float* __restrict__ h_new = g_h[(s + 1) & 1];

        // prefetch epilogue inputs (hidden behind the dot loop)
        const float* gip = gi_base + (size_t)s * GRU_G;
        float pre_ir = gip[0];
        float pre_ii = gip[GRU_H];
        float pre_in = gip[2 * GRU_H];
        float pre_hp = h_prev[ehoff];

        // ---- gh dot products: 12 rows x 8 batches per warp, lanes over K
        ull acc[96];
#pragma unroll
        for (int o = 0; o < 96; o++) acc[o] = 0ull;

#pragma unroll 4
        for (int t = 0; t < 16; t++) {
            const int k = (t * 32 + lane) * 2;       // f32x2 over adjacent k
            const float* hp = h_prev + hboff + k;
            const float* wp = Whh + k;
            ull h2[8];
#pragma unroll
            for (int b = 0; b < 8; b++)
                h2[b] = *(const ull*)(hp + b * GRU_H);
#pragma unroll
            for (int r = 0; r < 12; r++) {
                ull w2 = *(const ull*)(wp + rowoff[r]);
#pragma unroll
                for (int b = 0; b < 8; b++)
                    acc[r * 8 + b] = ffma2(w2, h2[b], acc[r * 8 + b]);
            }
        }

        // ---- warp reduce-scatter over lanes: lane l ends owning o=3l..3l+2
        RSTAGE(48, 16)
        RSTAGE(24, 8)
        RSTAGE(12, 4)
        RSTAGE(6, 2)
        RSTAGE(3, 1)

#pragma unroll
        for (int q = 0; q < 3; q++) {
            int o = lane * 3 + q;                  // o = r_local*8 + b_local
            ghs[rg * 12 + (o >> 3)][bg * 8 + (o & 7)] = sum2(acc[q]);
        }
        __syncthreads();

        // ---- fused gate epilogue: thread (ej, eb) -> one output element
        {
            float hr = ghs[ej][eb] + bh_r;
            float hi = ghs[8 + ej][eb] + bh_i;
            float hn = ghs[16 + ej][eb] + bh_n;

            float rgate = 1.0f / (1.0f + __expf(-(pre_ir + hr)));
            float zgate = 1.0f / (1.0f + __expf(-(pre_ii + hi)));
            float a = pre_in + rgate * hn;
            float e = __expf(-2.0f * a);
            float ng = __fdividef(1.0f - e, 1.0f + e);   // tanh(a)
            float hy = ng + zgate * (pre_hp - ng);

            h_new[ehoff] = hy;
            out_base[(size_t)s * GRU_H] = hy;
        }

        grid_barrier(tid, (unsigned)(s + 1));
    }
}

// ----------------------------------------------------------------------
__global__ void init_kernel() {
    int i = blockIdx.x * blockDim.x + threadIdx.x;
    if (i < GRU_B * GRU_H) g_h[0][i] = 0.0f;
    if (i == 0) { g_bar_count = 0u; g_bar_gen = 0u; }
}

// Final hidden state: after 512 steps, state lives in g_h[0] (512 even).
__global__ void copy_hlast_kernel(float* __restrict__ dst) {
    int i = blockIdx.x * blockDim.x + threadIdx.x;
    if (i < GRU_B * GRU_H) dst[i] = g_h[0][i];
}

// ----------------------------------------------------------------------
extern "C" void kernel_launch(void* const* d_in, const int* in_sizes, int n_in,
                              void* d_out, int out_size) {
    (void)in_sizes; (void)n_in; (void)out_size;
    const float* feats = (const float*)d_in[0];   // [B,S,D]
    const float* Wih   = (const float*)d_in[1];   // [3H,D]
    const float* Whh   = (const float*)d_in[2];   // [3H,H]
    const float* bih   = (const float*)d_in[3];   // [3H]
    const float* bhh   = (const float*)d_in[4];   // [3H]

    float* out   = (float*)d_out;                                  // [B,S,H]
    float* hlast = out + (size_t)GRU_B * GRU_S * GRU_H;            // [B,H]

    init_kernel<<<128, 256>>>();
    gemm_ih_kernel<<<dim3(GRU_G / 128, (GRU_B * GRU_S) / 128), 256>>>(feats, Wih, bih);
    gru_persistent_kernel<<<STEP_BLOCKS, 256>>>(Whh, bhh, out);
    copy_hlast_kernel<<<128, 256>>>(hlast);
}

// round 17
// speedup vs baseline: 1.0997x; 1.0997x over previous
#include <cuda_runtime.h>
#include <math.h>

// Problem constants: B=32, S=512, D=1024, H=1024, gates=3H=3072
#define GRU_B 32
#define GRU_S 512
#define GRU_D 1024
#define GRU_H 1024
#define GRU_G 3072

#define STEP_BLOCKS 128

typedef unsigned long long ull;

// Scratch (allocation-free rule: __device__ globals)
__device__ float g_gi[(size_t)GRU_B * GRU_S * GRU_G];   // [B,S,3H] input projections
__device__ float g_h[2][GRU_B * GRU_H];                  // ping-pong hidden state
__device__ unsigned g_bar_count;
__device__ unsigned g_bar_gen;

// ---------------- packed f32x2 helpers (sm_103a FFMA2) ----------------
__device__ __forceinline__ ull ffma2(ull a, ull b, ull c) {
    ull d;
    asm("fma.rn.f32x2 %0, %1, %2, %3;" : "=l"(d) : "l"(a), "l"(b), "l"(c));
    return d;
}
__device__ __forceinline__ ull add2(ull a, ull b) {
    ull d;
    asm("add.rn.f32x2 %0, %1, %2;" : "=l"(d) : "l"(a), "l"(b));
    return d;
}
__device__ __forceinline__ ull dup2(float x) {
    ull r;
    asm("mov.b64 %0, {%1, %1};" : "=l"(r) : "f"(x));
    return r;
}
union U2 { ull u; float2 f; };
__device__ __forceinline__ float sum2(ull v) {
    U2 t; t.u = v; return t.f.x + t.f.y;
}
__device__ __forceinline__ unsigned ld_acq_gpu(const unsigned* p) {
    unsigned v;
    asm volatile("ld.acquire.gpu.u32 %0, [%1];" : "=r"(v) : "l"(p) : "memory");
    return v;
}

// ----------------------------------------------------------------------
// Phase 1: gi = feats @ Wih^T + bias (unchanged — ~95% of FFMA2 roofline)
// ----------------------------------------------------------------------
__global__ void __launch_bounds__(256, 2) gemm_ih_kernel(
    const float* __restrict__ A,     // feats [M, 1024]
    const float* __restrict__ W,     // weight_ih [3072, 1024]
    const float* __restrict__ bias)  // bias_ih [3072]
{
    __shared__ __align__(16) float As[16][128];
    __shared__ __align__(16) float Bs[16][128];

    const int tid = threadIdx.x;
    const int bm = blockIdx.y * 128;
    const int bn = blockIdx.x * 128;
    const int tm = (tid >> 4) << 3;
    const int tn = (tid & 15) << 3;
    const int lm = tid >> 2;
    const int lk = (tid & 3) << 2;

    ull acc[8][4];
#pragma unroll
    for (int i = 0; i < 8; i++)
#pragma unroll
        for (int j = 0; j < 4; j++) acc[i][j] = 0ull;

    const float* Ap = A + (size_t)(bm + lm) * GRU_D + lk;
    const float* Wp = W + (size_t)(bn + lm) * GRU_D + lk;

    for (int k0 = 0; k0 < GRU_D; k0 += 16) {
        float4 a0 = *(const float4*)(Ap + k0);
        float4 a1 = *(const float4*)(Ap + k0 + (size_t)64 * GRU_D);
        float4 w0 = *(const float4*)(Wp + k0);
        float4 w1 = *(const float4*)(Wp + k0 + (size_t)64 * GRU_D);

        As[lk + 0][lm] = a0.x; As[lk + 1][lm] = a0.y;
        As[lk + 2][lm] = a0.z; As[lk + 3][lm] = a0.w;
        As[lk + 0][lm + 64] = a1.x; As[lk + 1][lm + 64] = a1.y;
        As[lk + 2][lm + 64] = a1.z; As[lk + 3][lm + 64] = a1.w;

        Bs[lk + 0][lm] = w0.x; Bs[lk + 1][lm] = w0.y;
        Bs[lk + 2][lm] = w0.z; Bs[lk + 3][lm] = w0.w;
        Bs[lk + 0][lm + 64] = w1.x; Bs[lk + 1][lm + 64] = w1.y;
        Bs[lk + 2][lm + 64] = w1.z; Bs[lk + 3][lm + 64] = w1.w;

        __syncthreads();

#pragma unroll
        for (int kk = 0; kk < 16; kk++) {
            float4 av0 = *(const float4*)&As[kk][tm];
            float4 av1 = *(const float4*)&As[kk][tm + 4];
            ulonglong2 bv0 = *(const ulonglong2*)&Bs[kk][tn];
            ulonglong2 bv1 = *(const ulonglong2*)&Bs[kk][tn + 4];
            float av[8] = {av0.x, av0.y, av0.z, av0.w, av1.x, av1.y, av1.z, av1.w};
#pragma unroll
            for (int i = 0; i < 8; i++) {
                ull ad = dup2(av[i]);
                acc[i][0] = ffma2(ad, bv0.x, acc[i][0]);
                acc[i][1] = ffma2(ad, bv0.y, acc[i][1]);
                acc[i][2] = ffma2(ad, bv1.x, acc[i][2]);
                acc[i][3] = ffma2(ad, bv1.y, acc[i][3]);
            }
        }
        __syncthreads();
    }

    float bz[8];
#pragma unroll
    for (int j = 0; j < 8; j++) bz[j] = bias[bn + tn + j];

#pragma unroll
    for (int i = 0; i < 8; i++) {
        float* Crow = g_gi + (size_t)(bm + tm + i) * GRU_G + bn + tn;
        U2 t0, t1, t2, t3;
        t0.u = acc[i][0]; t1.u = acc[i][1]; t2.u = acc[i][2]; t3.u = acc[i][3];
        float4 o0 = make_float4(t0.f.x + bz[0], t0.f.y + bz[1],
                                t1.f.x + bz[2], t1.f.y + bz[3]);
        float4 o1 = make_float4(t2.f.x + bz[4], t2.f.y + bz[5],
                                t3.f.x + bz[6], t3.f.y + bz[7]);
        *(float4*)(Crow + 0) = o0;
        *(float4*)(Crow + 4) = o1;
    }
}

// ----------------------------------------------------------------------
// Phase 2: PERSISTENT recurrence. 128 blocks x 256 threads (co-resident).
// Block owns 8 hidden cols = 24 Whh rows (L1-resident across steps).
// Warp tile: 12 rows x 8 batches, processed as TWO sequential passes of
// 12 rows x 4 batches so peak live accumulators = 48 f32x2 = 96 regs
// (the single-pass 192-reg version spilled). Lanes split K (coalesced),
// warp reduce-scatter via shfl, fused gate epilogue, grid barrier.
// ----------------------------------------------------------------------
__device__ __forceinline__ void grid_barrier(int tid, unsigned target) {
    __syncthreads();
    if (tid == 0) {
        __threadfence();
        unsigned old = atomicAdd(&g_bar_count, 1u);
        if (old == STEP_BLOCKS - 1) {
            atomicExch(&g_bar_count, 0u);
            __threadfence();
            atomicExch(&g_bar_gen, target);
        } else {
            while (ld_acq_gpu(&g_bar_gen) < target) { __nanosleep(16); }
            __threadfence();
        }
    }
    __syncthreads();
}

#define RSTAGE(HALF, SPAN)                                                   \
    {                                                                        \
        const bool up = (lane & (SPAN)) != 0;                                \
        _Pragma("unroll")                                                    \
        for (int i = 0; i < (HALF); i++) {                                   \
            ull keep = up ? acc[i + (HALF)] : acc[i];                        \
            ull send = up ? acc[i] : acc[i + (HALF)];                        \
            ull recv = __shfl_xor_sync(0xffffffffu, send, (SPAN));           \
            acc[i] = add2(keep, recv);                                       \
        }                                                                    \
    }

__global__ void __launch_bounds__(256, 1) gru_persistent_kernel(
    const float* __restrict__ Whh,      // [3072, 1024]
    const float* __restrict__ bias_hh,  // [3072]
    float* __restrict__ out,            // [B, S, H]
    float* __restrict__ hlast)          // [B, H]
{
    __shared__ float ghs[24][36];   // [local_row][batch], padded

    const int tid = threadIdx.x;
    const int warp = tid >> 5;
    const int lane = tid & 31;
    const int rg = warp >> 2;       // row group: 0 or 1 (12 rows each)
    const int bg = warp & 3;        // batch group: 8 batches each
    const int c0 = blockIdx.x * 8;  // hidden-column base

    // ---- epilogue mapping: ej = col, eb = batch
    const int ej = tid & 7;
    const int eb = tid >> 3;        // 0..31
    const float bh_r = bias_hh[c0 + ej];
    const float bh_i = bias_hh[GRU_H + c0 + ej];
    const float bh_n = bias_hh[2 * GRU_H + c0 + ej];
    const float* gi_base = g_gi + (size_t)eb * GRU_S * GRU_G + c0 + ej;
    float* out_base = out + (size_t)eb * GRU_S * GRU_H + c0 + ej;
    const int ehoff = eb * GRU_H + c0 + ej;

    // ---- dot-loop row offsets (floats) for this warp's 12 rows
    unsigned rowoff[12];
#pragma unroll
    for (int rr = 0; rr < 12; rr++) {
        int lr = rg * 12 + rr;             // local row 0..23
        int gate = lr >> 3, j = lr & 7;
        rowoff[rr] = (unsigned)(gate * (GRU_H * GRU_H) + (c0 + j) * GRU_H);
    }

    for (int s = 0; s < GRU_S; s++) {
        const float* __restrict__ h_prev = g_h[s & 1];
        float* __restrict__ h_new = g_h[(s + 1) & 1];

        // prefetch epilogue inputs (hidden behind the dot loops)
        const float* gip = gi_base + (size_t)s * GRU_G;
        float pre_ir = gip[0];
        float pre_ii = gip[GRU_H];
        float pre_in = gip[2 * GRU_H];
        float pre_hp = h_prev[ehoff];

        // ---- two passes of 12 rows x 4 batches (48 accs live at a time)
#pragma unroll
        for (int bh = 0; bh < 2; bh++) {
            const int bbase = bg * 8 + bh * 4;
            const int hboff = bbase * GRU_H;

            ull acc[48];
#pragma unroll
            for (int o = 0; o < 48; o++) acc[o] = 0ull;

#pragma unroll 4
            for (int t = 0; t < 16; t++) {
                const int k = (t * 32 + lane) * 2;   // f32x2 over adjacent k
                const float* hp = h_prev + hboff + k;
                const float* wp = Whh + k;
                ull h2[4];
#pragma unroll
                for (int b = 0; b < 4; b++)
                    h2[b] = *(const ull*)(hp + b * GRU_H);
#pragma unroll
                for (int r = 0; r < 12; r++) {
                    ull w2 = *(const ull*)(wp + rowoff[r]);
#pragma unroll
                    for (int b = 0; b < 4; b++)
                        acc[r * 4 + b] = ffma2(w2, h2[b], acc[r * 4 + b]);
                }
            }

            // ---- warp reduce-scatter: 48 accs -> 3 per lane-pair
            RSTAGE(24, 16)
            RSTAGE(12, 8)
            RSTAGE(6, 4)
            RSTAGE(3, 2)
            // final pairwise sum over bit0 (both lanes hold full result)
#pragma unroll
            for (int q = 0; q < 3; q++)
                acc[q] = add2(acc[q], __shfl_xor_sync(0xffffffffu, acc[q], 1));

            if ((lane & 1) == 0) {
                const int base = 3 * (lane >> 1);   // output o = r*4 + b
#pragma unroll
                for (int q = 0; q < 3; q++) {
                    int o = base + q;
                    ghs[rg * 12 + (o >> 2)][bbase + (o & 3)] = sum2(acc[q]);
                }
            }
        }
        __syncthreads();

        // ---- fused gate epilogue: thread (ej, eb) -> one output element
        {
            float hr = ghs[ej][eb] + bh_r;
            float hi = ghs[8 + ej][eb] + bh_i;
            float hn = ghs[16 + ej][eb] + bh_n;

            float rgate = 1.0f / (1.0f + __expf(-(pre_ir + hr)));
            float zgate = 1.0f / (1.0f + __expf(-(pre_ii + hi)));
            float a = pre_in + rgate * hn;
            float e = __expf(-2.0f * a);
            float ng = __fdividef(1.0f - e, 1.0f + e);   // tanh(a)
            float hy = ng + zgate * (pre_hp - ng);

            h_new[ehoff] = hy;
            out_base[(size_t)s * GRU_H] = hy;
            if (s == GRU_S - 1) hlast[ehoff] = hy;
        }

        grid_barrier(tid, (unsigned)(s + 1));
    }
}

// ----------------------------------------------------------------------
__global__ void init_kernel() {
    int i = blockIdx.x * blockDim.x + threadIdx.x;
    if (i < GRU_B * GRU_H) g_h[0][i] = 0.0f;
    if (i == 0) { g_bar_count = 0u; g_bar_gen = 0u; }
}

// ----------------------------------------------------------------------
extern "C" void kernel_launch(void* const* d_in, const int* in_sizes, int n_in,
                              void* d_out, int out_size) {
    (void)in_sizes; (void)n_in; (void)out_size;
    const float* feats = (const float*)d_in[0];   // [B,S,D]
    const float* Wih   = (const float*)d_in[1];   // [3H,D]
    const float* Whh   = (const float*)d_in[2];   // [3H,H]
    const float* bih   = (const float*)d_in[3];   // [3H]
    const float* bhh   = (const float*)d_in[4];   // [3H]

    float* out   = (float*)d_out;                                  // [B,S,H]
    float* hlast = out + (size_t)GRU_B * GRU_S * GRU_H;            // [B,H]

    init_kernel<<<128, 256>>>();
    gemm_ih_kernel<<<dim3(GRU_G / 128, (GRU_B * GRU_S) / 128), 256>>>(feats, Wih, bih);
    gru_persistent_kernel<<<STEP_BLOCKS, 256>>>(Whh, bhh, out, hlast);
}